// round 4
// baseline (speedup 1.0000x reference)
#include <cuda_runtime.h>
#include <cstdint>

#define H_HEADS 16
#define DHEAD 128
#define SEQ 2048
#define BATCH 2
#define CDIM 2048
#define WIN 256

// Scratch: Q,K,V in (B,H,L,D), attention output in (B,L,C)
__device__ float g_q[(size_t)BATCH * H_HEADS * SEQ * DHEAD];
__device__ float g_k[(size_t)BATCH * H_HEADS * SEQ * DHEAD];
__device__ float g_v[(size_t)BATCH * H_HEADS * SEQ * DHEAD];
__device__ float g_ao[(size_t)BATCH * SEQ * CDIM];

__device__ __forceinline__ uint32_t f2tf(float x) {
    uint32_t r;
    asm("cvt.rna.tf32.f32 %0, %1;" : "=r"(r) : "f"(x));
    return r;
}

__device__ __forceinline__ void mma8(float* c, const uint32_t* a, uint32_t b0, uint32_t b1) {
    asm volatile(
        "mma.sync.aligned.m16n8k8.row.col.f32.tf32.tf32.f32 "
        "{%0,%1,%2,%3},{%4,%5,%6,%7},{%8,%9},{%0,%1,%2,%3};\n"
        : "+f"(c[0]), "+f"(c[1]), "+f"(c[2]), "+f"(c[3])
        : "r"(a[0]), "r"(a[1]), "r"(a[2]), "r"(a[3]), "r"(b0), "r"(b1));
}

// ---------------------------------------------------------------------------
// TF32 GEMM, fragment-layout shared memory, zero cvt in the inner loop.
// out[m,n] = sum_k A[m,k]*W[n,k] + bias[n].  M=4096, N=2048, K=2048.
// Block tile 128x128x16, 8 warps (4x2), warp tile 32x64.
// mode 0: row-major out. mode 1: scatter to (B,H,L,D).
//
// A slot (k8, mg, g, tg, p): idx = ((k8*8+mg)*8+g)*16 + tg*4 + p
//   element (row, col): mg=row>>4, g=(row&15)&7, p=((row&15)>>3) + 2*((col&7)>>2), tg=(col&7)&3
// B slot (k8, ng, gn, tg, p): idx = ((k8*16+ng)*8+gn)*8 + tg*2 + p
//   element (n, k): ng=n>>3, gn=n&7, tg=(k&7)&3, p=(k&7)>>2
// ---------------------------------------------------------------------------
#define GK 2048
#define GN 2048
#define TBM 128
#define TBN 128
#define TBK 16
#define KT (GK / TBK)   // 128

__global__ __launch_bounds__(256, 2)
void gemm_frag(const float* __restrict__ A, const float* __restrict__ W,
               const float* __restrict__ bias, float* __restrict__ out, int mode)
{
    __shared__ uint32_t As[2][2048];
    __shared__ uint32_t Bs[2][2048];

    int tid = threadIdx.x;
    int wid = tid >> 5, lane = tid & 31;
    int g = lane >> 2, tg = lane & 3;
    int wm = wid >> 1, wn = wid & 1;
    int m0 = blockIdx.x * TBM;
    int n0 = blockIdx.y * TBN;

    // ---- producer constants: each thread owns 2 float4 of A and 2 of B ----
    int r0 = tid >> 2;               // 0..63
    int c0 = (tid & 3) * 4;          // 0,4,8,12
    int k8p = c0 >> 3, chp = (c0 >> 2) & 1;

    int mgA0 = r0 >> 4, grA0 = r0 & 15;
    int mgA1 = (r0 + 64) >> 4, grA1 = (r0 + 64) & 15;
    int idxA0 = ((k8p * 8 + mgA0) * 8 + (grA0 & 7)) * 16 + ((grA0 >> 3) + 2 * chp);
    int idxA1 = ((k8p * 8 + mgA1) * 8 + (grA1 & 7)) * 16 + ((grA1 >> 3) + 2 * chp);
    int idxB0 = ((k8p * 16 + (r0 >> 3)) * 8 + (r0 & 7)) * 8 + chp;
    int idxB1 = ((k8p * 16 + ((r0 + 64) >> 3)) * 8 + (r0 & 7)) * 8 + chp;

    const float* gA0 = A + (size_t)(m0 + r0) * GK + c0;
    const float* gA1 = gA0 + (size_t)64 * GK;
    const float* gB0 = W + (size_t)(n0 + r0) * GK + c0;
    const float* gB1 = gB0 + (size_t)64 * GK;

    // consumer base indices (FIX: mt stride is 8*16=128, not 256)
    int aBase0 = ((wm * 2 + 0) * 8 + g) * 16 + tg * 4;
    int aBase1 = aBase0 + 128;
    int bBase  = (wn * 8 * 8 + g) * 8 + tg * 2;

    float acc[2][8][4];
    #pragma unroll
    for (int mt = 0; mt < 2; mt++)
        #pragma unroll
        for (int nt = 0; nt < 8; nt++)
            #pragma unroll
            for (int i = 0; i < 4; i++) acc[mt][nt][i] = 0.f;

    float4 vA0, vA1, vB0, vB1;

    // prologue: tile 0
    vA0 = *(const float4*)gA0;  vA1 = *(const float4*)gA1;
    vB0 = *(const float4*)gB0;  vB1 = *(const float4*)gB1;
    {
        uint32_t* a = As[0];  uint32_t* b = Bs[0];
        a[idxA0] = f2tf(vA0.x); a[idxA0 + 4] = f2tf(vA0.y); a[idxA0 + 8] = f2tf(vA0.z); a[idxA0 + 12] = f2tf(vA0.w);
        a[idxA1] = f2tf(vA1.x); a[idxA1 + 4] = f2tf(vA1.y); a[idxA1 + 8] = f2tf(vA1.z); a[idxA1 + 12] = f2tf(vA1.w);
        b[idxB0] = f2tf(vB0.x); b[idxB0 + 2] = f2tf(vB0.y); b[idxB0 + 4] = f2tf(vB0.z); b[idxB0 + 6] = f2tf(vB0.w);
        b[idxB1] = f2tf(vB1.x); b[idxB1 + 2] = f2tf(vB1.y); b[idxB1 + 4] = f2tf(vB1.z); b[idxB1 + 6] = f2tf(vB1.w);
    }
    __syncthreads();

    for (int kt = 0; kt < KT; kt++) {
        int buf = kt & 1;
        if (kt + 1 < KT) {
            int off = (kt + 1) * TBK;
            vA0 = *(const float4*)(gA0 + off);
            vA1 = *(const float4*)(gA1 + off);
            vB0 = *(const float4*)(gB0 + off);
            vB1 = *(const float4*)(gB1 + off);
        }

        const uint32_t* as = As[buf];
        const uint32_t* bs = Bs[buf];
        #pragma unroll
        for (int k8 = 0; k8 < 2; k8++) {
            uint4 afr[2];
            afr[0] = *(const uint4*)&as[aBase0 + k8 * 1024];
            afr[1] = *(const uint4*)&as[aBase1 + k8 * 1024];
            #pragma unroll
            for (int nt = 0; nt < 8; nt++) {
                uint2 bfr = *(const uint2*)&bs[bBase + k8 * 1024 + nt * 64];
                mma8(acc[0][nt], (const uint32_t*)&afr[0], bfr.x, bfr.y);
                mma8(acc[1][nt], (const uint32_t*)&afr[1], bfr.x, bfr.y);
            }
        }

        if (kt + 1 < KT) {
            uint32_t* a = As[buf ^ 1];  uint32_t* b = Bs[buf ^ 1];
            a[idxA0] = f2tf(vA0.x); a[idxA0 + 4] = f2tf(vA0.y); a[idxA0 + 8] = f2tf(vA0.z); a[idxA0 + 12] = f2tf(vA0.w);
            a[idxA1] = f2tf(vA1.x); a[idxA1 + 4] = f2tf(vA1.y); a[idxA1 + 8] = f2tf(vA1.z); a[idxA1 + 12] = f2tf(vA1.w);
            b[idxB0] = f2tf(vB0.x); b[idxB0 + 2] = f2tf(vB0.y); b[idxB0 + 4] = f2tf(vB0.z); b[idxB0 + 6] = f2tf(vB0.w);
            b[idxB1] = f2tf(vB1.x); b[idxB1 + 2] = f2tf(vB1.y); b[idxB1 + 4] = f2tf(vB1.z); b[idxB1 + 6] = f2tf(vB1.w);
        }
        __syncthreads();
    }

    // epilogue
    #pragma unroll
    for (int mt = 0; mt < 2; mt++) {
        #pragma unroll
        for (int nt = 0; nt < 8; nt++) {
            int r = m0 + wm * 32 + mt * 16 + g;
            int c = n0 + wn * 64 + nt * 8 + 2 * tg;
            float bv0 = __ldg(&bias[c]), bv1 = __ldg(&bias[c + 1]);
            float v00 = acc[mt][nt][0] + bv0, v01 = acc[mt][nt][1] + bv1;
            float v10 = acc[mt][nt][2] + bv0, v11 = acc[mt][nt][3] + bv1;
            if (mode == 0) {
                *(float2*)&out[(size_t)r * GN + c]       = make_float2(v00, v01);
                *(float2*)&out[(size_t)(r + 8) * GN + c] = make_float2(v10, v11);
            } else {
                int b = r >> 11, l = r & 2047;
                int h = c >> 7, d = c & 127;
                size_t base = ((size_t)(b * H_HEADS + h) * SEQ + l) * DHEAD + d;
                *(float2*)&out[base]                     = make_float2(v00, v01);
                *(float2*)&out[base + (size_t)8 * DHEAD] = make_float2(v10, v11);
            }
        }
    }
}

// ---------------------------------------------------------------------------
// Sliding-window flash attention. K/V/P pre-converted to tf32 in smem.
// ---------------------------------------------------------------------------
#define KSTR 132
#define VSTR 136
#define SSTR 68
#define ATT_SMEM ((64 * KSTR + 64 * VSTR + 128 * SSTR) * 4)

__global__ __launch_bounds__(256, 1)
void attn_win(const float* __restrict__ qg, const float* __restrict__ kg,
              const float* __restrict__ vg, float* __restrict__ aout)
{
    extern __shared__ uint32_t sm[];
    uint32_t* Ks = sm;
    uint32_t* Vs = sm + 64 * KSTR;
    uint32_t* Ss = Vs + 64 * VSTR;

    int tid = threadIdx.x;
    int wid = tid >> 5, lane = tid & 31, g = lane >> 2, tg = lane & 3;
    int q0 = blockIdx.x * 128;
    int bh = blockIdx.y;
    const float* qb = qg + (size_t)bh * SEQ * DHEAD;
    const float* kb = kg + (size_t)bh * SEQ * DHEAD;
    const float* vb = vg + (size_t)bh * SEQ * DHEAD;
    int b = bh >> 4, h = bh & 15;

    uint32_t qa[16][4];
    int qr = q0 + wid * 16 + g;
    #pragma unroll
    for (int ks = 0; ks < 16; ks++) {
        int c = ks * 8 + tg;
        qa[ks][0] = f2tf(__ldg(&qb[(size_t)qr * DHEAD + c]));
        qa[ks][1] = f2tf(__ldg(&qb[(size_t)(qr + 8) * DHEAD + c]));
        qa[ks][2] = f2tf(__ldg(&qb[(size_t)qr * DHEAD + c + 4]));
        qa[ks][3] = f2tf(__ldg(&qb[(size_t)(qr + 8) * DHEAD + c + 4]));
    }

    float o[16][4];
    #pragma unroll
    for (int nt = 0; nt < 16; nt++)
        #pragma unroll
        for (int i = 0; i < 4; i++) o[nt][i] = 0.f;
    float mrow0 = -1e30f, mrow1 = -1e30f, lsum0 = 0.f, lsum1 = 0.f;

    const float scale = 0.088388347648318447f;
    const int offs[6] = {0, 1, -1, -2, -3, -4};

    for (int ci = 0; ci < 6; ci++) {
        int k0 = q0 + offs[ci] * 64;
        if (k0 < 0) continue;
        __syncthreads();
        #pragma unroll
        for (int e = tid; e < 64 * 32; e += 256) {
            int r = e >> 5, c4 = e & 31;
            float4 kv = *(const float4*)&kb[(size_t)(k0 + r) * DHEAD + c4 * 4];
            float4 vv = *(const float4*)&vb[(size_t)(k0 + r) * DHEAD + c4 * 4];
            *(uint4*)&Ks[r * KSTR + c4 * 4] = make_uint4(f2tf(kv.x), f2tf(kv.y), f2tf(kv.z), f2tf(kv.w));
            *(uint4*)&Vs[r * VSTR + c4 * 4] = make_uint4(f2tf(vv.x), f2tf(vv.y), f2tf(vv.z), f2tf(vv.w));
        }
        __syncthreads();

        float s[8][4];
        #pragma unroll
        for (int nt = 0; nt < 8; nt++)
            #pragma unroll
            for (int i = 0; i < 4; i++) s[nt][i] = 0.f;
        #pragma unroll
        for (int ks = 0; ks < 16; ks++) {
            int c = ks * 8 + tg;
            #pragma unroll
            for (int nt = 0; nt < 8; nt++) {
                int n = nt * 8 + g;
                mma8(s[nt], qa[ks], Ks[n * KSTR + c], Ks[n * KSTR + c + 4]);
            }
        }

        int i0 = q0 + wid * 16 + g, i1 = i0 + 8;
        float mx0 = -1e30f, mx1 = -1e30f;
        #pragma unroll
        for (int nt = 0; nt < 8; nt++) {
            int j0 = k0 + nt * 8 + 2 * tg, j1 = j0 + 1;
            s[nt][0] = ((j0 <= i0) && (j0 > i0 - WIN)) ? s[nt][0] * scale : -1e30f;
            s[nt][1] = ((j1 <= i0) && (j1 > i0 - WIN)) ? s[nt][1] * scale : -1e30f;
            s[nt][2] = ((j0 <= i1) && (j0 > i1 - WIN)) ? s[nt][2] * scale : -1e30f;
            s[nt][3] = ((j1 <= i1) && (j1 > i1 - WIN)) ? s[nt][3] * scale : -1e30f;
            mx0 = fmaxf(mx0, fmaxf(s[nt][0], s[nt][1]));
            mx1 = fmaxf(mx1, fmaxf(s[nt][2], s[nt][3]));
        }
        mx0 = fmaxf(mx0, __shfl_xor_sync(0xffffffffu, mx0, 1));
        mx0 = fmaxf(mx0, __shfl_xor_sync(0xffffffffu, mx0, 2));
        mx1 = fmaxf(mx1, __shfl_xor_sync(0xffffffffu, mx1, 1));
        mx1 = fmaxf(mx1, __shfl_xor_sync(0xffffffffu, mx1, 2));
        float mn0 = fmaxf(mrow0, mx0), mn1 = fmaxf(mrow1, mx1);
        float al0 = __expf(mrow0 - mn0), al1 = __expf(mrow1 - mn1);
        mrow0 = mn0; mrow1 = mn1;

        float rs0 = 0.f, rs1 = 0.f;
        #pragma unroll
        for (int nt = 0; nt < 8; nt++) {
            s[nt][0] = __expf(s[nt][0] - mn0);
            s[nt][1] = __expf(s[nt][1] - mn0);
            s[nt][2] = __expf(s[nt][2] - mn1);
            s[nt][3] = __expf(s[nt][3] - mn1);
            rs0 += s[nt][0] + s[nt][1];
            rs1 += s[nt][2] + s[nt][3];
        }
        rs0 += __shfl_xor_sync(0xffffffffu, rs0, 1);
        rs0 += __shfl_xor_sync(0xffffffffu, rs0, 2);
        rs1 += __shfl_xor_sync(0xffffffffu, rs1, 1);
        rs1 += __shfl_xor_sync(0xffffffffu, rs1, 2);
        lsum0 = lsum0 * al0 + rs0;
        lsum1 = lsum1 * al1 + rs1;

        int pr0 = wid * 16 + g, pr1 = pr0 + 8;
        #pragma unroll
        for (int nt = 0; nt < 8; nt++) {
            int cc = nt * 8 + 2 * tg;
            Ss[pr0 * SSTR + cc]     = f2tf(s[nt][0]);
            Ss[pr0 * SSTR + cc + 1] = f2tf(s[nt][1]);
            Ss[pr1 * SSTR + cc]     = f2tf(s[nt][2]);
            Ss[pr1 * SSTR + cc + 1] = f2tf(s[nt][3]);
        }
        __syncwarp();

        #pragma unroll
        for (int nt = 0; nt < 16; nt++) {
            o[nt][0] *= al0; o[nt][1] *= al0;
            o[nt][2] *= al1; o[nt][3] *= al1;
        }

        #pragma unroll
        for (int ks = 0; ks < 8; ks++) {
            uint32_t pa[4];
            int pc = ks * 8 + tg;
            pa[0] = Ss[pr0 * SSTR + pc];
            pa[1] = Ss[pr1 * SSTR + pc];
            pa[2] = Ss[pr0 * SSTR + pc + 4];
            pa[3] = Ss[pr1 * SSTR + pc + 4];
            #pragma unroll
            for (int nt = 0; nt < 16; nt++) {
                int d = nt * 8 + g;
                int kk = ks * 8 + tg;
                mma8(o[nt], pa, Vs[kk * VSTR + d], Vs[(kk + 4) * VSTR + d]);
            }
        }
    }

    float inv0 = 1.f / lsum0, inv1 = 1.f / lsum1;
    int t0 = q0 + wid * 16 + g;
    #pragma unroll
    for (int nt = 0; nt < 16; nt++) {
        int col = h * DHEAD + nt * 8 + 2 * tg;
        *(float2*)&aout[((size_t)b * SEQ + t0) * CDIM + col] =
            make_float2(o[nt][0] * inv0, o[nt][1] * inv0);
        *(float2*)&aout[((size_t)b * SEQ + t0 + 8) * CDIM + col] =
            make_float2(o[nt][2] * inv1, o[nt][3] * inv1);
    }
}

// ---------------------------------------------------------------------------
extern "C" void kernel_launch(void* const* d_in, const int* in_sizes, int n_in,
                              void* d_out, int out_size)
{
    const float* x  = (const float*)d_in[0];
    const float* Wq = (const float*)d_in[1];
    const float* bq = (const float*)d_in[2];
    const float* Wk = (const float*)d_in[3];
    const float* bk = (const float*)d_in[4];
    const float* Wv = (const float*)d_in[5];
    const float* bv = (const float*)d_in[6];
    const float* Wo = (const float*)d_in[7];
    const float* bo = (const float*)d_in[8];
    float* out = (float*)d_out;

    float *qp, *kp, *vp, *aop;
    cudaGetSymbolAddress((void**)&qp, g_q);
    cudaGetSymbolAddress((void**)&kp, g_k);
    cudaGetSymbolAddress((void**)&vp, g_v);
    cudaGetSymbolAddress((void**)&aop, g_ao);

    cudaFuncSetAttribute(attn_win, cudaFuncAttributeMaxDynamicSharedMemorySize, ATT_SMEM);

    const int M = BATCH * SEQ;      // 4096
    dim3 gg(M / TBM, GN / TBN);     // 32 x 16

    gemm_frag<<<gg, 256>>>(x, Wq, bq, qp, 1);
    gemm_frag<<<gg, 256>>>(x, Wk, bk, kp, 1);
    gemm_frag<<<gg, 256>>>(x, Wv, bv, vp, 1);
    attn_win<<<dim3(SEQ / 128, BATCH * H_HEADS), 256, ATT_SMEM>>>(qp, kp, vp, aop);
    gemm_frag<<<gg, 256>>>(aop, Wo, bo, out, 0);
}

// round 5
// speedup vs baseline: 1.4013x; 1.4013x over previous
#include <cuda_runtime.h>
#include <cuda_fp16.h>
#include <cstdint>

#define H_HEADS 16
#define DHEAD 128
#define SEQ 2048
#define BATCH 2
#define CDIM 2048
#define WIN 256

// Scratch: Q,K,V in (B,H,L,D), attention output in (B,L,C)
__device__ float g_q[(size_t)BATCH * H_HEADS * SEQ * DHEAD];
__device__ float g_k[(size_t)BATCH * H_HEADS * SEQ * DHEAD];
__device__ float g_v[(size_t)BATCH * H_HEADS * SEQ * DHEAD];
__device__ float g_ao[(size_t)BATCH * SEQ * CDIM];

__device__ __forceinline__ uint32_t f2tf(float x) {
    uint32_t r;
    asm("cvt.rna.tf32.f32 %0, %1;" : "=r"(r) : "f"(x));
    return r;
}

__device__ __forceinline__ void mma8(float* c, const uint32_t* a, uint32_t b0, uint32_t b1) {
    asm volatile(
        "mma.sync.aligned.m16n8k8.row.col.f32.tf32.tf32.f32 "
        "{%0,%1,%2,%3},{%4,%5,%6,%7},{%8,%9},{%0,%1,%2,%3};\n"
        : "+f"(c[0]), "+f"(c[1]), "+f"(c[2]), "+f"(c[3])
        : "r"(a[0]), "r"(a[1]), "r"(a[2]), "r"(a[3]), "r"(b0), "r"(b1));
}

__device__ __forceinline__ void mma16(float* c, const uint32_t* a, uint32_t b0, uint32_t b1) {
    asm volatile(
        "mma.sync.aligned.m16n8k16.row.col.f32.f16.f16.f32 "
        "{%0,%1,%2,%3},{%4,%5,%6,%7},{%8,%9},{%0,%1,%2,%3};\n"
        : "+f"(c[0]), "+f"(c[1]), "+f"(c[2]), "+f"(c[3])
        : "r"(a[0]), "r"(a[1]), "r"(a[2]), "r"(a[3]), "r"(b0), "r"(b1));
}

__device__ __forceinline__ void ldsm4(uint32_t* r, uint32_t addr) {
    asm volatile("ldmatrix.sync.aligned.m8n8.x4.shared.b16 {%0,%1,%2,%3}, [%4];"
                 : "=r"(r[0]), "=r"(r[1]), "=r"(r[2]), "=r"(r[3]) : "r"(addr));
}

__device__ __forceinline__ void sts128(uint32_t addr, uint4 u) {
    asm volatile("st.shared.v4.b32 [%0], {%1,%2,%3,%4};"
                 :: "r"(addr), "r"(u.x), "r"(u.y), "r"(u.z), "r"(u.w) : "memory");
}

__device__ __forceinline__ uint32_t smem_u32(const void* p) {
    uint32_t a;
    asm("{ .reg .u64 t; cvta.to.shared.u64 t, %1; cvt.u32.u64 %0, t; }" : "=r"(a) : "l"(p));
    return a;
}

__device__ __forceinline__ uint32_t pk(float x, float y) {
    __half2 h = __floats2half2_rn(x, y);
    return *(uint32_t*)&h;
}

// ---------------------------------------------------------------------------
// FP16 GEMM with ldmatrix. out[m,n] = sum_k A[m,k]*W[n,k] + bias[n].
// M=4096, N=2048, K=2048. Block tile 128x128x32, 8 warps (4x2), warp 32x64.
// Smem tile: 64 smem-rows x 128B; smem-row s holds m-rows {2s, 2s+1} (32 halves
// each = 4 chunks of 16B). chunk = ((m&1)*4 + k/8) ^ (s&7)  (conflict-free for
// ldmatrix 8-row phases and STS.128 store phases).
// mode 0: row-major out. mode 1: scatter to (B,H,L,D).
// ---------------------------------------------------------------------------
#define GK 2048
#define GN 2048
#define TBM 128
#define TBN 128
#define BK 32
#define KT (GK / BK)   // 64
#define TILE_BYTES 8192

__global__ __launch_bounds__(256, 2)
void gemm_h16(const float* __restrict__ A, const float* __restrict__ W,
              const float* __restrict__ bias, float* __restrict__ out, int mode)
{
    __shared__ __align__(16) char smA[2][TILE_BYTES];
    __shared__ __align__(16) char smB[2][TILE_BYTES];

    int tid = threadIdx.x;
    int wid = tid >> 5, lane = tid & 31;
    int g = lane >> 2, tg = lane & 3;
    int wm = wid >> 1, wn = wid & 1;
    int m0 = blockIdx.x * TBM;
    int n0 = blockIdx.y * TBN;

    uint32_t aBase = smem_u32(smA[0]);
    uint32_t bBase = smem_u32(smB[0]);

    // ---- producer constants: thread owns 16 halves of one A row + one B row ----
    int pm = tid >> 1;                 // row 0..127
    int kh = (tid & 1) * 16;           // k offset (halves)
    const float* gA = A + (size_t)(m0 + pm) * GK + kh;
    const float* gB = W + (size_t)(n0 + pm) * GK + kh;
    int ps = pm >> 1;
    int pre0 = (pm & 1) * 4 + (tid & 1) * 2;
    uint32_t pOff0 = (uint32_t)(ps * 128 + ((pre0 ^ (ps & 7)) * 16));
    uint32_t pOff1 = (uint32_t)(ps * 128 + (((pre0 + 1) ^ (ps & 7)) * 16));

    // ---- consumer ldmatrix addresses (kstep 0; kstep 1 = addr ^ 32) ----
    uint32_t aAdr[2], bAdr[4];
    #pragma unroll
    for (int mt = 0; mt < 2; mt++) {
        int m = wm * 32 + mt * 16 + (lane & 7) + 8 * ((lane >> 3) & 1);
        int k8 = lane >> 4;            // 0..1
        int s = m >> 1;
        int chunk = (((m & 1) * 4 + k8) ^ (s & 7));
        aAdr[mt] = (uint32_t)(s * 128 + chunk * 16);
    }
    #pragma unroll
    for (int nq = 0; nq < 4; nq++) {
        int n = wn * 64 + nq * 16 + (lane & 7) + 8 * (lane >> 4);
        int k8 = (lane >> 3) & 1;
        int s = n >> 1;
        int chunk = (((n & 1) * 4 + k8) ^ (s & 7));
        bAdr[nq] = (uint32_t)(s * 128 + chunk * 16);
    }

    float acc[2][8][4];
    #pragma unroll
    for (int mt = 0; mt < 2; mt++)
        #pragma unroll
        for (int nt = 0; nt < 8; nt++)
            #pragma unroll
            for (int i = 0; i < 4; i++) acc[mt][nt][i] = 0.f;

    float4 fa[4], fb[4];

    // prologue: tile 0
    #pragma unroll
    for (int j = 0; j < 4; j++) {
        fa[j] = *(const float4*)(gA + j * 4);
        fb[j] = *(const float4*)(gB + j * 4);
    }
    {
        uint32_t a0 = aBase + pOff0, a1 = aBase + pOff1;
        uint32_t b0 = bBase + pOff0, b1 = bBase + pOff1;
        sts128(a0, make_uint4(pk(fa[0].x, fa[0].y), pk(fa[0].z, fa[0].w), pk(fa[1].x, fa[1].y), pk(fa[1].z, fa[1].w)));
        sts128(a1, make_uint4(pk(fa[2].x, fa[2].y), pk(fa[2].z, fa[2].w), pk(fa[3].x, fa[3].y), pk(fa[3].z, fa[3].w)));
        sts128(b0, make_uint4(pk(fb[0].x, fb[0].y), pk(fb[0].z, fb[0].w), pk(fb[1].x, fb[1].y), pk(fb[1].z, fb[1].w)));
        sts128(b1, make_uint4(pk(fb[2].x, fb[2].y), pk(fb[2].z, fb[2].w), pk(fb[3].x, fb[3].y), pk(fb[3].z, fb[3].w)));
    }
    __syncthreads();

    for (int kt = 0; kt < KT; kt++) {
        int buf = kt & 1;
        if (kt + 1 < KT) {
            int off = (kt + 1) * BK;
            #pragma unroll
            for (int j = 0; j < 4; j++) {
                fa[j] = *(const float4*)(gA + off + j * 4);
                fb[j] = *(const float4*)(gB + off + j * 4);
            }
        }

        uint32_t ab = aBase + buf * TILE_BYTES;
        uint32_t bb = bBase + buf * TILE_BYTES;
        #pragma unroll
        for (int ks = 0; ks < 2; ks++) {
            uint32_t kx = ks ? 32u : 0u;
            uint32_t af0[4], af1[4];
            ldsm4(af0, ab + (aAdr[0] ^ kx));
            ldsm4(af1, ab + (aAdr[1] ^ kx));
            #pragma unroll
            for (int nq = 0; nq < 4; nq++) {
                uint32_t bf[4];
                ldsm4(bf, bb + (bAdr[nq] ^ kx));
                mma16(acc[0][2 * nq],     af0, bf[0], bf[1]);
                mma16(acc[0][2 * nq + 1], af0, bf[2], bf[3]);
                mma16(acc[1][2 * nq],     af1, bf[0], bf[1]);
                mma16(acc[1][2 * nq + 1], af1, bf[2], bf[3]);
            }
        }

        if (kt + 1 < KT) {
            uint32_t a0 = aBase + (buf ^ 1) * TILE_BYTES + pOff0, a1 = aBase + (buf ^ 1) * TILE_BYTES + pOff1;
            uint32_t b0 = bBase + (buf ^ 1) * TILE_BYTES + pOff0, b1 = bBase + (buf ^ 1) * TILE_BYTES + pOff1;
            sts128(a0, make_uint4(pk(fa[0].x, fa[0].y), pk(fa[0].z, fa[0].w), pk(fa[1].x, fa[1].y), pk(fa[1].z, fa[1].w)));
            sts128(a1, make_uint4(pk(fa[2].x, fa[2].y), pk(fa[2].z, fa[2].w), pk(fa[3].x, fa[3].y), pk(fa[3].z, fa[3].w)));
            sts128(b0, make_uint4(pk(fb[0].x, fb[0].y), pk(fb[0].z, fb[0].w), pk(fb[1].x, fb[1].y), pk(fb[1].z, fb[1].w)));
            sts128(b1, make_uint4(pk(fb[2].x, fb[2].y), pk(fb[2].z, fb[2].w), pk(fb[3].x, fb[3].y), pk(fb[3].z, fb[3].w)));
        }
        __syncthreads();
    }

    // epilogue
    #pragma unroll
    for (int mt = 0; mt < 2; mt++) {
        #pragma unroll
        for (int nt = 0; nt < 8; nt++) {
            int r = m0 + wm * 32 + mt * 16 + g;
            int c = n0 + wn * 64 + nt * 8 + 2 * tg;
            float bv0 = __ldg(&bias[c]), bv1 = __ldg(&bias[c + 1]);
            float v00 = acc[mt][nt][0] + bv0, v01 = acc[mt][nt][1] + bv1;
            float v10 = acc[mt][nt][2] + bv0, v11 = acc[mt][nt][3] + bv1;
            if (mode == 0) {
                *(float2*)&out[(size_t)r * GN + c]       = make_float2(v00, v01);
                *(float2*)&out[(size_t)(r + 8) * GN + c] = make_float2(v10, v11);
            } else {
                int b = r >> 11, l = r & 2047;
                int h = c >> 7, d = c & 127;
                size_t base = ((size_t)(b * H_HEADS + h) * SEQ + l) * DHEAD + d;
                *(float2*)&out[base]                     = make_float2(v00, v01);
                *(float2*)&out[base + (size_t)8 * DHEAD] = make_float2(v10, v11);
            }
        }
    }
}

// ---------------------------------------------------------------------------
// Sliding-window flash attention (tf32, unchanged from round 4 - 131us).
// ---------------------------------------------------------------------------
#define KSTR 132
#define VSTR 136
#define SSTR 68
#define ATT_SMEM ((64 * KSTR + 64 * VSTR + 128 * SSTR) * 4)

__global__ __launch_bounds__(256, 1)
void attn_win(const float* __restrict__ qg, const float* __restrict__ kg,
              const float* __restrict__ vg, float* __restrict__ aout)
{
    extern __shared__ uint32_t sm[];
    uint32_t* Ks = sm;
    uint32_t* Vs = sm + 64 * KSTR;
    uint32_t* Ss = Vs + 64 * VSTR;

    int tid = threadIdx.x;
    int wid = tid >> 5, lane = tid & 31, g = lane >> 2, tg = lane & 3;
    int q0 = blockIdx.x * 128;
    int bh = blockIdx.y;
    const float* qb = qg + (size_t)bh * SEQ * DHEAD;
    const float* kb = kg + (size_t)bh * SEQ * DHEAD;
    const float* vb = vg + (size_t)bh * SEQ * DHEAD;
    int b = bh >> 4, h = bh & 15;

    uint32_t qa[16][4];
    int qr = q0 + wid * 16 + g;
    #pragma unroll
    for (int ks = 0; ks < 16; ks++) {
        int c = ks * 8 + tg;
        qa[ks][0] = f2tf(__ldg(&qb[(size_t)qr * DHEAD + c]));
        qa[ks][1] = f2tf(__ldg(&qb[(size_t)(qr + 8) * DHEAD + c]));
        qa[ks][2] = f2tf(__ldg(&qb[(size_t)qr * DHEAD + c + 4]));
        qa[ks][3] = f2tf(__ldg(&qb[(size_t)(qr + 8) * DHEAD + c + 4]));
    }

    float o[16][4];
    #pragma unroll
    for (int nt = 0; nt < 16; nt++)
        #pragma unroll
        for (int i = 0; i < 4; i++) o[nt][i] = 0.f;
    float mrow0 = -1e30f, mrow1 = -1e30f, lsum0 = 0.f, lsum1 = 0.f;

    const float scale = 0.088388347648318447f;
    const int offs[6] = {0, 1, -1, -2, -3, -4};

    for (int ci = 0; ci < 6; ci++) {
        int k0 = q0 + offs[ci] * 64;
        if (k0 < 0) continue;
        __syncthreads();
        #pragma unroll
        for (int e = tid; e < 64 * 32; e += 256) {
            int r = e >> 5, c4 = e & 31;
            float4 kv = *(const float4*)&kb[(size_t)(k0 + r) * DHEAD + c4 * 4];
            float4 vv = *(const float4*)&vb[(size_t)(k0 + r) * DHEAD + c4 * 4];
            *(uint4*)&Ks[r * KSTR + c4 * 4] = make_uint4(f2tf(kv.x), f2tf(kv.y), f2tf(kv.z), f2tf(kv.w));
            *(uint4*)&Vs[r * VSTR + c4 * 4] = make_uint4(f2tf(vv.x), f2tf(vv.y), f2tf(vv.z), f2tf(vv.w));
        }
        __syncthreads();

        float s[8][4];
        #pragma unroll
        for (int nt = 0; nt < 8; nt++)
            #pragma unroll
            for (int i = 0; i < 4; i++) s[nt][i] = 0.f;
        #pragma unroll
        for (int ks = 0; ks < 16; ks++) {
            int c = ks * 8 + tg;
            #pragma unroll
            for (int nt = 0; nt < 8; nt++) {
                int n = nt * 8 + g;
                mma8(s[nt], qa[ks], Ks[n * KSTR + c], Ks[n * KSTR + c + 4]);
            }
        }

        int i0 = q0 + wid * 16 + g, i1 = i0 + 8;
        float mx0 = -1e30f, mx1 = -1e30f;
        #pragma unroll
        for (int nt = 0; nt < 8; nt++) {
            int j0 = k0 + nt * 8 + 2 * tg, j1 = j0 + 1;
            s[nt][0] = ((j0 <= i0) && (j0 > i0 - WIN)) ? s[nt][0] * scale : -1e30f;
            s[nt][1] = ((j1 <= i0) && (j1 > i0 - WIN)) ? s[nt][1] * scale : -1e30f;
            s[nt][2] = ((j0 <= i1) && (j0 > i1 - WIN)) ? s[nt][2] * scale : -1e30f;
            s[nt][3] = ((j1 <= i1) && (j1 > i1 - WIN)) ? s[nt][3] * scale : -1e30f;
            mx0 = fmaxf(mx0, fmaxf(s[nt][0], s[nt][1]));
            mx1 = fmaxf(mx1, fmaxf(s[nt][2], s[nt][3]));
        }
        mx0 = fmaxf(mx0, __shfl_xor_sync(0xffffffffu, mx0, 1));
        mx0 = fmaxf(mx0, __shfl_xor_sync(0xffffffffu, mx0, 2));
        mx1 = fmaxf(mx1, __shfl_xor_sync(0xffffffffu, mx1, 1));
        mx1 = fmaxf(mx1, __shfl_xor_sync(0xffffffffu, mx1, 2));
        float mn0 = fmaxf(mrow0, mx0), mn1 = fmaxf(mrow1, mx1);
        float al0 = __expf(mrow0 - mn0), al1 = __expf(mrow1 - mn1);
        mrow0 = mn0; mrow1 = mn1;

        float rs0 = 0.f, rs1 = 0.f;
        #pragma unroll
        for (int nt = 0; nt < 8; nt++) {
            s[nt][0] = __expf(s[nt][0] - mn0);
            s[nt][1] = __expf(s[nt][1] - mn0);
            s[nt][2] = __expf(s[nt][2] - mn1);
            s[nt][3] = __expf(s[nt][3] - mn1);
            rs0 += s[nt][0] + s[nt][1];
            rs1 += s[nt][2] + s[nt][3];
        }
        rs0 += __shfl_xor_sync(0xffffffffu, rs0, 1);
        rs0 += __shfl_xor_sync(0xffffffffu, rs0, 2);
        rs1 += __shfl_xor_sync(0xffffffffu, rs1, 1);
        rs1 += __shfl_xor_sync(0xffffffffu, rs1, 2);
        lsum0 = lsum0 * al0 + rs0;
        lsum1 = lsum1 * al1 + rs1;

        int pr0 = wid * 16 + g, pr1 = pr0 + 8;
        #pragma unroll
        for (int nt = 0; nt < 8; nt++) {
            int cc = nt * 8 + 2 * tg;
            Ss[pr0 * SSTR + cc]     = f2tf(s[nt][0]);
            Ss[pr0 * SSTR + cc + 1] = f2tf(s[nt][1]);
            Ss[pr1 * SSTR + cc]     = f2tf(s[nt][2]);
            Ss[pr1 * SSTR + cc + 1] = f2tf(s[nt][3]);
        }
        __syncwarp();

        #pragma unroll
        for (int nt = 0; nt < 16; nt++) {
            o[nt][0] *= al0; o[nt][1] *= al0;
            o[nt][2] *= al1; o[nt][3] *= al1;
        }

        #pragma unroll
        for (int ks = 0; ks < 8; ks++) {
            uint32_t pa[4];
            int pc = ks * 8 + tg;
            pa[0] = Ss[pr0 * SSTR + pc];
            pa[1] = Ss[pr1 * SSTR + pc];
            pa[2] = Ss[pr0 * SSTR + pc + 4];
            pa[3] = Ss[pr1 * SSTR + pc + 4];
            #pragma unroll
            for (int nt = 0; nt < 16; nt++) {
                int d = nt * 8 + g;
                int kk = ks * 8 + tg;
                mma8(o[nt], pa, Vs[kk * VSTR + d], Vs[(kk + 4) * VSTR + d]);
            }
        }
    }

    float inv0 = 1.f / lsum0, inv1 = 1.f / lsum1;
    int t0 = q0 + wid * 16 + g;
    #pragma unroll
    for (int nt = 0; nt < 16; nt++) {
        int col = h * DHEAD + nt * 8 + 2 * tg;
        *(float2*)&aout[((size_t)b * SEQ + t0) * CDIM + col] =
            make_float2(o[nt][0] * inv0, o[nt][1] * inv0);
        *(float2*)&aout[((size_t)b * SEQ + t0 + 8) * CDIM + col] =
            make_float2(o[nt][2] * inv1, o[nt][3] * inv1);
    }
}

// ---------------------------------------------------------------------------
extern "C" void kernel_launch(void* const* d_in, const int* in_sizes, int n_in,
                              void* d_out, int out_size)
{
    const float* x  = (const float*)d_in[0];
    const float* Wq = (const float*)d_in[1];
    const float* bq = (const float*)d_in[2];
    const float* Wk = (const float*)d_in[3];
    const float* bk = (const float*)d_in[4];
    const float* Wv = (const float*)d_in[5];
    const float* bv = (const float*)d_in[6];
    const float* Wo = (const float*)d_in[7];
    const float* bo = (const float*)d_in[8];
    float* out = (float*)d_out;

    float *qp, *kp, *vp, *aop;
    cudaGetSymbolAddress((void**)&qp, g_q);
    cudaGetSymbolAddress((void**)&kp, g_k);
    cudaGetSymbolAddress((void**)&vp, g_v);
    cudaGetSymbolAddress((void**)&aop, g_ao);

    cudaFuncSetAttribute(attn_win, cudaFuncAttributeMaxDynamicSharedMemorySize, ATT_SMEM);

    const int M = BATCH * SEQ;      // 4096
    dim3 gg(M / TBM, GN / TBN);     // 32 x 16

    gemm_h16<<<gg, 256>>>(x, Wq, bq, qp, 1);
    gemm_h16<<<gg, 256>>>(x, Wk, bk, kp, 1);
    gemm_h16<<<gg, 256>>>(x, Wv, bv, vp, 1);
    attn_win<<<dim3(SEQ / 128, BATCH * H_HEADS), 256, ATT_SMEM>>>(qp, kp, vp, aop);
    gemm_h16<<<gg, 256>>>(aop, Wo, bo, out, 0);
}

// round 8
// speedup vs baseline: 3.0508x; 2.1770x over previous
#include <cuda_runtime.h>
#include <cuda_fp16.h>
#include <cstdint>

#define H_HEADS 16
#define DHEAD 128
#define SEQ 2048
#define BATCH 2
#define CDIM 2048
#define WIN 256

#define GK 2048
#define GN 2048
#define GM 4096

#define QKV_ELEMS ((size_t)BATCH * H_HEADS * SEQ * DHEAD)   // 8388608
#define WMAT_ELEMS ((size_t)GK * GN)                        // 4194304

// fp32 scratch
__device__ float g_qkv[3 * QKV_ELEMS];
// fp16 scratch
__device__ __half g_xh[(size_t)GM * GK];
__device__ __half g_wh[4 * WMAT_ELEMS];      // Wq,Wk,Wv,Wo
__device__ __half g_aoh[(size_t)GM * CDIM];

// ---------------------------------------------------------------------------
__device__ __forceinline__ uint32_t f2tf(float x) {
    uint32_t r;
    asm("cvt.rna.tf32.f32 %0, %1;" : "=r"(r) : "f"(x));
    return r;
}

__device__ __forceinline__ void mma8(float* c, const uint32_t* a, uint32_t b0, uint32_t b1) {
    asm volatile(
        "mma.sync.aligned.m16n8k8.row.col.f32.tf32.tf32.f32 "
        "{%0,%1,%2,%3},{%4,%5,%6,%7},{%8,%9},{%0,%1,%2,%3};\n"
        : "+f"(c[0]), "+f"(c[1]), "+f"(c[2]), "+f"(c[3])
        : "r"(a[0]), "r"(a[1]), "r"(a[2]), "r"(a[3]), "r"(b0), "r"(b1));
}

__device__ __forceinline__ void mma16(float* c, const uint32_t* a, uint32_t b0, uint32_t b1) {
    asm volatile(
        "mma.sync.aligned.m16n8k16.row.col.f32.f16.f16.f32 "
        "{%0,%1,%2,%3},{%4,%5,%6,%7},{%8,%9},{%0,%1,%2,%3};\n"
        : "+f"(c[0]), "+f"(c[1]), "+f"(c[2]), "+f"(c[3])
        : "r"(a[0]), "r"(a[1]), "r"(a[2]), "r"(a[3]), "r"(b0), "r"(b1));
}

__device__ __forceinline__ void ldsm4(uint32_t* r, uint32_t addr) {
    asm volatile("ldmatrix.sync.aligned.m8n8.x4.shared.b16 {%0,%1,%2,%3}, [%4];"
                 : "=r"(r[0]), "=r"(r[1]), "=r"(r[2]), "=r"(r[3]) : "r"(addr));
}

__device__ __forceinline__ uint32_t smem_u32(const void* p) {
    uint32_t a;
    asm("{ .reg .u64 t; cvta.to.shared.u64 t, %1; cvt.u32.u64 %0, t; }" : "=r"(a) : "l"(p));
    return a;
}

__device__ __forceinline__ void cp16(uint32_t dst, const void* src) {
    asm volatile("cp.async.cg.shared.global [%0], [%1], 16;\n" :: "r"(dst), "l"(src));
}
__device__ __forceinline__ void cp_commit() { asm volatile("cp.async.commit_group;\n"); }
template<int N> __device__ __forceinline__ void cp_wait() {
    asm volatile("cp.async.wait_group %0;\n" :: "n"(N));
}

// ---------------------------------------------------------------------------
// fp32 -> fp16 conversion (vectorized, grid-strided by construction of launch)
// ---------------------------------------------------------------------------
__global__ void cvt_h(const float* __restrict__ in, __half* __restrict__ out, int n)
{
    int i = (blockIdx.x * blockDim.x + threadIdx.x) * 8;
    if (i < n) {
        float4 a = *(const float4*)(in + i);
        float4 b = *(const float4*)(in + i + 4);
        __half2 h0 = __floats2half2_rn(a.x, a.y);
        __half2 h1 = __floats2half2_rn(a.z, a.w);
        __half2 h2 = __floats2half2_rn(b.x, b.y);
        __half2 h3 = __floats2half2_rn(b.z, b.w);
        uint4 u = make_uint4(*(uint32_t*)&h0, *(uint32_t*)&h1, *(uint32_t*)&h2, *(uint32_t*)&h3);
        *(uint4*)(out + i) = u;
    }
}

// ---------------------------------------------------------------------------
// FP16 GEMM, cp.async 4-stage pipeline + ldmatrix.
// out[m,n] = sum_k A[m,k]*W[n,k] + bias[n].  Tile 128x128x32, 8 warps (4x2).
// Smem tile: 64 smem-rows x 128B; smem-row s holds rows {2s,2s+1} (4 chunks of
// 16B each); chunk = ((m&1)*4 + k8) ^ (s&7).
// fused=1: blockIdx.y in [0,48) -> matrix mi=y/16 (Wq/Wk/Wv), scatter (B,H,L,D)
//          into out + mi*QKV_ELEMS.
// fused=0: row-major fp32 out.
// ---------------------------------------------------------------------------
#define TBM 128
#define TBN 128
#define BK 32
#define KT (GK / BK)      // 64
#define TILE_BYTES 8192
#define NST 4
#define GEMM_SMEM (NST * 2 * TILE_BYTES)   // 64 KB

__global__ __launch_bounds__(256, 2)
void gemm_ca(const __half* __restrict__ A, const __half* __restrict__ Wh,
             const float* __restrict__ bias0, const float* __restrict__ bias1,
             const float* __restrict__ bias2, float* __restrict__ out, int fused)
{
    extern __shared__ __align__(16) char smem[];
    uint32_t sbase = smem_u32(smem);

    int tid = threadIdx.x;
    int wid = tid >> 5, lane = tid & 31;
    int g = lane >> 2, tg = lane & 3;
    int wm = wid >> 1, wn = wid & 1;
    int m0 = blockIdx.x * TBM;

    int mi = 0, n0;
    const float* bias = bias0;
    const __half* W = Wh;
    float* outp = out;
    if (fused) {
        mi = blockIdx.y >> 4;
        n0 = (blockIdx.y & 15) * TBN;
        W = Wh + (size_t)mi * WMAT_ELEMS;
        bias = (mi == 0) ? bias0 : (mi == 1) ? bias1 : bias2;
        outp = out + (size_t)mi * QKV_ELEMS;
    } else {
        n0 = blockIdx.y * TBN;
    }

    // ---- producer constants: 2 A-chunks + 2 B-chunks of 16B per thread ----
    int pm = tid >> 1;
    int ps = pm >> 1;
    int pre0 = (pm & 1) * 4 + (tid & 1) * 2;
    uint32_t pOff0 = (uint32_t)(ps * 128 + ((pre0 ^ (ps & 7)) * 16));
    uint32_t pOff1 = (uint32_t)(ps * 128 + (((pre0 + 1) ^ (ps & 7)) * 16));
    const __half* gA = A + (size_t)(m0 + pm) * GK + (tid & 1) * 16;
    const __half* gW = W + (size_t)(n0 + pm) * GK + (tid & 1) * 16;

    // ---- consumer ldmatrix addresses ----
    uint32_t aAdr[2], bAdr[4];
    #pragma unroll
    for (int mt = 0; mt < 2; mt++) {
        int m = wm * 32 + mt * 16 + (lane & 7) + 8 * ((lane >> 3) & 1);
        int k8 = lane >> 4;
        int s = m >> 1;
        int chunk = (((m & 1) * 4 + k8) ^ (s & 7));
        aAdr[mt] = (uint32_t)(s * 128 + chunk * 16);
    }
    #pragma unroll
    for (int nq = 0; nq < 4; nq++) {
        int n = wn * 64 + nq * 16 + (lane & 7) + 8 * (lane >> 4);
        int k8 = (lane >> 3) & 1;
        int s = n >> 1;
        int chunk = (((n & 1) * 4 + k8) ^ (s & 7));
        bAdr[nq] = (uint32_t)(s * 128 + chunk * 16);
    }

    float acc[2][8][4];
    #pragma unroll
    for (int mt = 0; mt < 2; mt++)
        #pragma unroll
        for (int nt = 0; nt < 8; nt++)
            #pragma unroll
            for (int i = 0; i < 4; i++) acc[mt][nt][i] = 0.f;

    // prologue: issue stages 0..2
    #pragma unroll
    for (int s = 0; s < NST - 1; s++) {
        uint32_t aT = sbase + s * (2 * TILE_BYTES);
        uint32_t bT = aT + TILE_BYTES;
        const __half* sa = gA + s * BK;
        const __half* sb = gW + s * BK;
        cp16(aT + pOff0, sa);
        cp16(aT + pOff1, sa + 8);
        cp16(bT + pOff0, sb);
        cp16(bT + pOff1, sb + 8);
        cp_commit();
    }

    for (int kt = 0; kt < KT; kt++) {
        cp_wait<NST - 2>();
        __syncthreads();

        // issue load for kt+3
        if (kt + NST - 1 < KT) {
            int st = (kt + NST - 1) & (NST - 1);
            uint32_t aT = sbase + st * (2 * TILE_BYTES);
            uint32_t bT = aT + TILE_BYTES;
            const __half* sa = gA + (kt + NST - 1) * BK;
            const __half* sb = gW + (kt + NST - 1) * BK;
            cp16(aT + pOff0, sa);
            cp16(aT + pOff1, sa + 8);
            cp16(bT + pOff0, sb);
            cp16(bT + pOff1, sb + 8);
        }
        cp_commit();

        int buf = kt & (NST - 1);
        uint32_t ab = sbase + buf * (2 * TILE_BYTES);
        uint32_t bb = ab + TILE_BYTES;
        #pragma unroll
        for (int ks = 0; ks < 2; ks++) {
            uint32_t kx = ks ? 32u : 0u;
            uint32_t af0[4], af1[4];
            ldsm4(af0, ab + (aAdr[0] ^ kx));
            ldsm4(af1, ab + (aAdr[1] ^ kx));
            #pragma unroll
            for (int nq = 0; nq < 4; nq++) {
                uint32_t bf[4];
                ldsm4(bf, bb + (bAdr[nq] ^ kx));
                mma16(acc[0][2 * nq],     af0, bf[0], bf[1]);
                mma16(acc[0][2 * nq + 1], af0, bf[2], bf[3]);
                mma16(acc[1][2 * nq],     af1, bf[0], bf[1]);
                mma16(acc[1][2 * nq + 1], af1, bf[2], bf[3]);
            }
        }
    }

    // epilogue
    #pragma unroll
    for (int mt = 0; mt < 2; mt++) {
        #pragma unroll
        for (int nt = 0; nt < 8; nt++) {
            int r = m0 + wm * 32 + mt * 16 + g;
            int c = n0 + wn * 64 + nt * 8 + 2 * tg;
            float bv0 = __ldg(&bias[c]), bv1 = __ldg(&bias[c + 1]);
            float v00 = acc[mt][nt][0] + bv0, v01 = acc[mt][nt][1] + bv1;
            float v10 = acc[mt][nt][2] + bv0, v11 = acc[mt][nt][3] + bv1;
            if (!fused) {
                *(float2*)&outp[(size_t)r * GN + c]       = make_float2(v00, v01);
                *(float2*)&outp[(size_t)(r + 8) * GN + c] = make_float2(v10, v11);
            } else {
                int b = r >> 11, l = r & 2047;
                int h = c >> 7, d = c & 127;
                size_t base = ((size_t)(b * H_HEADS + h) * SEQ + l) * DHEAD + d;
                *(float2*)&outp[base]                     = make_float2(v00, v01);
                *(float2*)&outp[base + (size_t)8 * DHEAD] = make_float2(v10, v11);
            }
        }
    }
}

// ---------------------------------------------------------------------------
// Sliding-window flash attention (tf32). Writes fp16 output for final GEMM.
// ---------------------------------------------------------------------------
#define KSTR 132
#define VSTR 136
#define SSTR 68
#define ATT_SMEM ((64 * KSTR + 64 * VSTR + 128 * SSTR) * 4)

__global__ __launch_bounds__(256, 1)
void attn_win(const float* __restrict__ qg, const float* __restrict__ kg,
              const float* __restrict__ vg, __half* __restrict__ aout)
{
    extern __shared__ uint32_t sm[];
    uint32_t* Ks = sm;
    uint32_t* Vs = sm + 64 * KSTR;
    uint32_t* Ss = Vs + 64 * VSTR;

    int tid = threadIdx.x;
    int wid = tid >> 5, lane = tid & 31, g = lane >> 2, tg = lane & 3;
    int q0 = blockIdx.x * 128;
    int bh = blockIdx.y;
    const float* qb = qg + (size_t)bh * SEQ * DHEAD;
    const float* kb = kg + (size_t)bh * SEQ * DHEAD;
    const float* vb = vg + (size_t)bh * SEQ * DHEAD;
    int b = bh >> 4, h = bh & 15;

    uint32_t qa[16][4];
    int qr = q0 + wid * 16 + g;
    #pragma unroll
    for (int ks = 0; ks < 16; ks++) {
        int c = ks * 8 + tg;
        qa[ks][0] = f2tf(__ldg(&qb[(size_t)qr * DHEAD + c]));
        qa[ks][1] = f2tf(__ldg(&qb[(size_t)(qr + 8) * DHEAD + c]));
        qa[ks][2] = f2tf(__ldg(&qb[(size_t)qr * DHEAD + c + 4]));
        qa[ks][3] = f2tf(__ldg(&qb[(size_t)(qr + 8) * DHEAD + c + 4]));
    }

    float o[16][4];
    #pragma unroll
    for (int nt = 0; nt < 16; nt++)
        #pragma unroll
        for (int i = 0; i < 4; i++) o[nt][i] = 0.f;
    float mrow0 = -1e30f, mrow1 = -1e30f, lsum0 = 0.f, lsum1 = 0.f;

    const float scale = 0.088388347648318447f;
    const int offs[6] = {0, 1, -1, -2, -3, -4};

    for (int ci = 0; ci < 6; ci++) {
        int k0 = q0 + offs[ci] * 64;
        if (k0 < 0) continue;
        __syncthreads();
        #pragma unroll
        for (int e = tid; e < 64 * 32; e += 256) {
            int r = e >> 5, c4 = e & 31;
            float4 kv = *(const float4*)&kb[(size_t)(k0 + r) * DHEAD + c4 * 4];
            float4 vv = *(const float4*)&vb[(size_t)(k0 + r) * DHEAD + c4 * 4];
            *(uint4*)&Ks[r * KSTR + c4 * 4] = make_uint4(f2tf(kv.x), f2tf(kv.y), f2tf(kv.z), f2tf(kv.w));
            *(uint4*)&Vs[r * VSTR + c4 * 4] = make_uint4(f2tf(vv.x), f2tf(vv.y), f2tf(vv.z), f2tf(vv.w));
        }
        __syncthreads();

        float s[8][4];
        #pragma unroll
        for (int nt = 0; nt < 8; nt++)
            #pragma unroll
            for (int i = 0; i < 4; i++) s[nt][i] = 0.f;
        #pragma unroll
        for (int ks = 0; ks < 16; ks++) {
            int c = ks * 8 + tg;
            #pragma unroll
            for (int nt = 0; nt < 8; nt++) {
                int n = nt * 8 + g;
                mma8(s[nt], qa[ks], Ks[n * KSTR + c], Ks[n * KSTR + c + 4]);
            }
        }

        int i0 = q0 + wid * 16 + g, i1 = i0 + 8;
        float mx0 = -1e30f, mx1 = -1e30f;
        #pragma unroll
        for (int nt = 0; nt < 8; nt++) {
            int j0 = k0 + nt * 8 + 2 * tg, j1 = j0 + 1;
            s[nt][0] = ((j0 <= i0) && (j0 > i0 - WIN)) ? s[nt][0] * scale : -1e30f;
            s[nt][1] = ((j1 <= i0) && (j1 > i0 - WIN)) ? s[nt][1] * scale : -1e30f;
            s[nt][2] = ((j0 <= i1) && (j0 > i1 - WIN)) ? s[nt][2] * scale : -1e30f;
            s[nt][3] = ((j1 <= i1) && (j1 > i1 - WIN)) ? s[nt][3] * scale : -1e30f;
            mx0 = fmaxf(mx0, fmaxf(s[nt][0], s[nt][1]));
            mx1 = fmaxf(mx1, fmaxf(s[nt][2], s[nt][3]));
        }
        mx0 = fmaxf(mx0, __shfl_xor_sync(0xffffffffu, mx0, 1));
        mx0 = fmaxf(mx0, __shfl_xor_sync(0xffffffffu, mx0, 2));
        mx1 = fmaxf(mx1, __shfl_xor_sync(0xffffffffu, mx1, 1));
        mx1 = fmaxf(mx1, __shfl_xor_sync(0xffffffffu, mx1, 2));
        float mn0 = fmaxf(mrow0, mx0), mn1 = fmaxf(mrow1, mx1);
        float al0 = __expf(mrow0 - mn0), al1 = __expf(mrow1 - mn1);
        mrow0 = mn0; mrow1 = mn1;

        float rs0 = 0.f, rs1 = 0.f;
        #pragma unroll
        for (int nt = 0; nt < 8; nt++) {
            s[nt][0] = __expf(s[nt][0] - mn0);
            s[nt][1] = __expf(s[nt][1] - mn0);
            s[nt][2] = __expf(s[nt][2] - mn1);
            s[nt][3] = __expf(s[nt][3] - mn1);
            rs0 += s[nt][0] + s[nt][1];
            rs1 += s[nt][2] + s[nt][3];
        }
        rs0 += __shfl_xor_sync(0xffffffffu, rs0, 1);
        rs0 += __shfl_xor_sync(0xffffffffu, rs0, 2);
        rs1 += __shfl_xor_sync(0xffffffffu, rs1, 1);
        rs1 += __shfl_xor_sync(0xffffffffu, rs1, 2);
        lsum0 = lsum0 * al0 + rs0;
        lsum1 = lsum1 * al1 + rs1;

        int pr0 = wid * 16 + g, pr1 = pr0 + 8;
        #pragma unroll
        for (int nt = 0; nt < 8; nt++) {
            int cc = nt * 8 + 2 * tg;
            Ss[pr0 * SSTR + cc]     = f2tf(s[nt][0]);
            Ss[pr0 * SSTR + cc + 1] = f2tf(s[nt][1]);
            Ss[pr1 * SSTR + cc]     = f2tf(s[nt][2]);
            Ss[pr1 * SSTR + cc + 1] = f2tf(s[nt][3]);
        }
        __syncwarp();

        #pragma unroll
        for (int nt = 0; nt < 16; nt++) {
            o[nt][0] *= al0; o[nt][1] *= al0;
            o[nt][2] *= al1; o[nt][3] *= al1;
        }

        #pragma unroll
        for (int ks = 0; ks < 8; ks++) {
            uint32_t pa[4];
            int pc = ks * 8 + tg;
            pa[0] = Ss[pr0 * SSTR + pc];
            pa[1] = Ss[pr1 * SSTR + pc];
            pa[2] = Ss[pr0 * SSTR + pc + 4];
            pa[3] = Ss[pr1 * SSTR + pc + 4];
            #pragma unroll
            for (int nt = 0; nt < 16; nt++) {
                int d = nt * 8 + g;
                int kk = ks * 8 + tg;
                mma8(o[nt], pa, Vs[kk * VSTR + d], Vs[(kk + 4) * VSTR + d]);
            }
        }
    }

    float inv0 = 1.f / lsum0, inv1 = 1.f / lsum1;
    int t0 = q0 + wid * 16 + g;
    #pragma unroll
    for (int nt = 0; nt < 16; nt++) {
        int col = h * DHEAD + nt * 8 + 2 * tg;
        __half2 h0 = __floats2half2_rn(o[nt][0] * inv0, o[nt][1] * inv0);
        __half2 h1 = __floats2half2_rn(o[nt][2] * inv1, o[nt][3] * inv1);
        *(__half2*)&aout[((size_t)b * SEQ + t0) * CDIM + col]     = h0;
        *(__half2*)&aout[((size_t)b * SEQ + t0 + 8) * CDIM + col] = h1;
    }
}

// ---------------------------------------------------------------------------
extern "C" void kernel_launch(void* const* d_in, const int* in_sizes, int n_in,
                              void* d_out, int out_size)
{
    const float* x  = (const float*)d_in[0];
    const float* Wq = (const float*)d_in[1];
    const float* bq = (const float*)d_in[2];
    const float* Wk = (const float*)d_in[3];
    const float* bk = (const float*)d_in[4];
    const float* Wv = (const float*)d_in[5];
    const float* bv = (const float*)d_in[6];
    const float* Wo = (const float*)d_in[7];
    const float* bo = (const float*)d_in[8];
    float* out = (float*)d_out;

    float* qkvp;
    __half *xh, *wh, *aoh;
    cudaGetSymbolAddress((void**)&qkvp, g_qkv);
    cudaGetSymbolAddress((void**)&xh, g_xh);
    cudaGetSymbolAddress((void**)&wh, g_wh);
    cudaGetSymbolAddress((void**)&aoh, g_aoh);

    cudaFuncSetAttribute(gemm_ca, cudaFuncAttributeMaxDynamicSharedMemorySize, GEMM_SMEM);
    cudaFuncSetAttribute(attn_win, cudaFuncAttributeMaxDynamicSharedMemorySize, ATT_SMEM);

    // fp32 -> fp16 conversions
    const int XEL = GM * GK;          // 8388608
    const int WEL = (int)WMAT_ELEMS;  // 4194304
    cvt_h<<<XEL / 8 / 256, 256>>>(x, xh, XEL);
    cvt_h<<<WEL / 8 / 256, 256>>>(Wq, wh + 0 * WMAT_ELEMS, WEL);
    cvt_h<<<WEL / 8 / 256, 256>>>(Wk, wh + 1 * WMAT_ELEMS, WEL);
    cvt_h<<<WEL / 8 / 256, 256>>>(Wv, wh + 2 * WMAT_ELEMS, WEL);
    cvt_h<<<WEL / 8 / 256, 256>>>(Wo, wh + 3 * WMAT_ELEMS, WEL);

    // fused QKV GEMM: grid (32, 48)
    gemm_ca<<<dim3(GM / TBM, 48), 256, GEMM_SMEM>>>(xh, wh, bq, bk, bv, qkvp, 1);

    // attention
    attn_win<<<dim3(SEQ / 128, BATCH * H_HEADS), 256, ATT_SMEM>>>(
        qkvp, qkvp + QKV_ELEMS, qkvp + 2 * QKV_ELEMS, aoh);

    // output projection
    gemm_ca<<<dim3(GM / TBM, GN / TBN), 256, GEMM_SMEM>>>(
        aoh, wh + 3 * WMAT_ELEMS, bo, nullptr, nullptr, out, 0);
}

// round 9
// speedup vs baseline: 3.4486x; 1.1304x over previous
#include <cuda_runtime.h>
#include <cuda_fp16.h>
#include <cstdint>

#define H_HEADS 16
#define DHEAD 128
#define SEQ 2048
#define BATCH 2
#define CDIM 2048
#define WIN 256

#define GK 2048
#define GN 2048
#define GM 4096

#define QKV_ELEMS ((size_t)BATCH * H_HEADS * SEQ * DHEAD)   // 8388608
#define WMAT_ELEMS ((size_t)GK * GN)                        // 4194304

// fp16 scratch
__device__ __half g_qkvh[3 * QKV_ELEMS];     // Q,K,V in (B,H,L,D)
__device__ __half g_xh[(size_t)GM * GK];
__device__ __half g_wh[4 * WMAT_ELEMS];      // Wq,Wk,Wv,Wo
__device__ __half g_aoh[(size_t)GM * CDIM];

// ---------------------------------------------------------------------------
__device__ __forceinline__ void mma16(float* c, const uint32_t* a, uint32_t b0, uint32_t b1) {
    asm volatile(
        "mma.sync.aligned.m16n8k16.row.col.f32.f16.f16.f32 "
        "{%0,%1,%2,%3},{%4,%5,%6,%7},{%8,%9},{%0,%1,%2,%3};\n"
        : "+f"(c[0]), "+f"(c[1]), "+f"(c[2]), "+f"(c[3])
        : "r"(a[0]), "r"(a[1]), "r"(a[2]), "r"(a[3]), "r"(b0), "r"(b1));
}

__device__ __forceinline__ void ldsm4(uint32_t* r, uint32_t addr) {
    asm volatile("ldmatrix.sync.aligned.m8n8.x4.shared.b16 {%0,%1,%2,%3}, [%4];"
                 : "=r"(r[0]), "=r"(r[1]), "=r"(r[2]), "=r"(r[3]) : "r"(addr));
}
__device__ __forceinline__ void ldsm4t(uint32_t* r, uint32_t addr) {
    asm volatile("ldmatrix.sync.aligned.m8n8.x4.trans.shared.b16 {%0,%1,%2,%3}, [%4];"
                 : "=r"(r[0]), "=r"(r[1]), "=r"(r[2]), "=r"(r[3]) : "r"(addr));
}

__device__ __forceinline__ uint32_t smem_u32(const void* p) {
    uint32_t a;
    asm("{ .reg .u64 t; cvta.to.shared.u64 t, %1; cvt.u32.u64 %0, t; }" : "=r"(a) : "l"(p));
    return a;
}

__device__ __forceinline__ void cp16(uint32_t dst, const void* src) {
    asm volatile("cp.async.cg.shared.global [%0], [%1], 16;\n" :: "r"(dst), "l"(src));
}
__device__ __forceinline__ void cp_commit() { asm volatile("cp.async.commit_group;\n"); }
template<int N> __device__ __forceinline__ void cp_wait() {
    asm volatile("cp.async.wait_group %0;\n" :: "n"(N));
}

// ---------------------------------------------------------------------------
// fp32 -> fp16 conversions
// ---------------------------------------------------------------------------
__global__ void cvt_h(const float* __restrict__ in, __half* __restrict__ out, int n)
{
    int i = (blockIdx.x * blockDim.x + threadIdx.x) * 8;
    if (i < n) {
        float4 a = *(const float4*)(in + i);
        float4 b = *(const float4*)(in + i + 4);
        __half2 h0 = __floats2half2_rn(a.x, a.y);
        __half2 h1 = __floats2half2_rn(a.z, a.w);
        __half2 h2 = __floats2half2_rn(b.x, b.y);
        __half2 h3 = __floats2half2_rn(b.z, b.w);
        *(uint4*)(out + i) = make_uint4(*(uint32_t*)&h0, *(uint32_t*)&h1,
                                        *(uint32_t*)&h2, *(uint32_t*)&h3);
    }
}

__global__ void cvt_w4(const float* __restrict__ w0, const float* __restrict__ w1,
                       const float* __restrict__ w2, const float* __restrict__ w3,
                       __half* __restrict__ out)
{
    int m = blockIdx.y;
    const float* in = (m == 0) ? w0 : (m == 1) ? w1 : (m == 2) ? w2 : w3;
    __half* o = out + (size_t)m * WMAT_ELEMS;
    int i = (blockIdx.x * blockDim.x + threadIdx.x) * 8;
    float4 a = *(const float4*)(in + i);
    float4 b = *(const float4*)(in + i + 4);
    __half2 h0 = __floats2half2_rn(a.x, a.y);
    __half2 h1 = __floats2half2_rn(a.z, a.w);
    __half2 h2 = __floats2half2_rn(b.x, b.y);
    __half2 h3 = __floats2half2_rn(b.z, b.w);
    *(uint4*)(o + i) = make_uint4(*(uint32_t*)&h0, *(uint32_t*)&h1,
                                  *(uint32_t*)&h2, *(uint32_t*)&h3);
}

// ---------------------------------------------------------------------------
// FP16 GEMM, cp.async 4-stage pipeline + ldmatrix (proven round-8 core).
// fused=1: grid.y in [0,48): matrix mi=y/16 -> fp16 scatter (B,H,L,D).
// fused=0: fp32 row-major out.
// ---------------------------------------------------------------------------
#define TBM 128
#define TBN 128
#define BK 32
#define KT (GK / BK)      // 64
#define TILE_BYTES 8192
#define NST 4
#define GEMM_SMEM (NST * 2 * TILE_BYTES)   // 64 KB

__global__ __launch_bounds__(256, 2)
void gemm_ca(const __half* __restrict__ A, const __half* __restrict__ Wh,
             const float* __restrict__ bias0, const float* __restrict__ bias1,
             const float* __restrict__ bias2,
             float* __restrict__ outf, __half* __restrict__ outh, int fused)
{
    extern __shared__ __align__(16) char smem[];
    uint32_t sbase = smem_u32(smem);

    int tid = threadIdx.x;
    int wid = tid >> 5, lane = tid & 31;
    int g = lane >> 2, tg = lane & 3;
    int wm = wid >> 1, wn = wid & 1;
    int m0 = blockIdx.x * TBM;

    int n0;
    const float* bias = bias0;
    const __half* W = Wh;
    __half* outp = outh;
    if (fused) {
        int mi = blockIdx.y >> 4;
        n0 = (blockIdx.y & 15) * TBN;
        W = Wh + (size_t)mi * WMAT_ELEMS;
        bias = (mi == 0) ? bias0 : (mi == 1) ? bias1 : bias2;
        outp = outh + (size_t)mi * QKV_ELEMS;
    } else {
        n0 = blockIdx.y * TBN;
    }

    int pm = tid >> 1;
    int ps = pm >> 1;
    int pre0 = (pm & 1) * 4 + (tid & 1) * 2;
    uint32_t pOff0 = (uint32_t)(ps * 128 + ((pre0 ^ (ps & 7)) * 16));
    uint32_t pOff1 = (uint32_t)(ps * 128 + (((pre0 + 1) ^ (ps & 7)) * 16));
    const __half* gA = A + (size_t)(m0 + pm) * GK + (tid & 1) * 16;
    const __half* gW = W + (size_t)(n0 + pm) * GK + (tid & 1) * 16;

    uint32_t aAdr[2], bAdr[4];
    #pragma unroll
    for (int mt = 0; mt < 2; mt++) {
        int m = wm * 32 + mt * 16 + (lane & 7) + 8 * ((lane >> 3) & 1);
        int k8 = lane >> 4;
        int s = m >> 1;
        int chunk = (((m & 1) * 4 + k8) ^ (s & 7));
        aAdr[mt] = (uint32_t)(s * 128 + chunk * 16);
    }
    #pragma unroll
    for (int nq = 0; nq < 4; nq++) {
        int n = wn * 64 + nq * 16 + (lane & 7) + 8 * (lane >> 4);
        int k8 = (lane >> 3) & 1;
        int s = n >> 1;
        int chunk = (((n & 1) * 4 + k8) ^ (s & 7));
        bAdr[nq] = (uint32_t)(s * 128 + chunk * 16);
    }

    float acc[2][8][4];
    #pragma unroll
    for (int mt = 0; mt < 2; mt++)
        #pragma unroll
        for (int nt = 0; nt < 8; nt++)
            #pragma unroll
            for (int i = 0; i < 4; i++) acc[mt][nt][i] = 0.f;

    #pragma unroll
    for (int s = 0; s < NST - 1; s++) {
        uint32_t aT = sbase + s * (2 * TILE_BYTES);
        uint32_t bT = aT + TILE_BYTES;
        const __half* sa = gA + s * BK;
        const __half* sb = gW + s * BK;
        cp16(aT + pOff0, sa);
        cp16(aT + pOff1, sa + 8);
        cp16(bT + pOff0, sb);
        cp16(bT + pOff1, sb + 8);
        cp_commit();
    }

    for (int kt = 0; kt < KT; kt++) {
        cp_wait<NST - 2>();
        __syncthreads();

        if (kt + NST - 1 < KT) {
            int st = (kt + NST - 1) & (NST - 1);
            uint32_t aT = sbase + st * (2 * TILE_BYTES);
            uint32_t bT = aT + TILE_BYTES;
            const __half* sa = gA + (kt + NST - 1) * BK;
            const __half* sb = gW + (kt + NST - 1) * BK;
            cp16(aT + pOff0, sa);
            cp16(aT + pOff1, sa + 8);
            cp16(bT + pOff0, sb);
            cp16(bT + pOff1, sb + 8);
        }
        cp_commit();

        int buf = kt & (NST - 1);
        uint32_t ab = sbase + buf * (2 * TILE_BYTES);
        uint32_t bb = ab + TILE_BYTES;
        #pragma unroll
        for (int ks = 0; ks < 2; ks++) {
            uint32_t kx = ks ? 32u : 0u;
            uint32_t af0[4], af1[4];
            ldsm4(af0, ab + (aAdr[0] ^ kx));
            ldsm4(af1, ab + (aAdr[1] ^ kx));
            #pragma unroll
            for (int nq = 0; nq < 4; nq++) {
                uint32_t bf[4];
                ldsm4(bf, bb + (bAdr[nq] ^ kx));
                mma16(acc[0][2 * nq],     af0, bf[0], bf[1]);
                mma16(acc[0][2 * nq + 1], af0, bf[2], bf[3]);
                mma16(acc[1][2 * nq],     af1, bf[0], bf[1]);
                mma16(acc[1][2 * nq + 1], af1, bf[2], bf[3]);
            }
        }
    }

    #pragma unroll
    for (int mt = 0; mt < 2; mt++) {
        #pragma unroll
        for (int nt = 0; nt < 8; nt++) {
            int r = m0 + wm * 32 + mt * 16 + g;
            int c = n0 + wn * 64 + nt * 8 + 2 * tg;
            float bv0 = __ldg(&bias[c]), bv1 = __ldg(&bias[c + 1]);
            float v00 = acc[mt][nt][0] + bv0, v01 = acc[mt][nt][1] + bv1;
            float v10 = acc[mt][nt][2] + bv0, v11 = acc[mt][nt][3] + bv1;
            if (!fused) {
                *(float2*)&outf[(size_t)r * GN + c]       = make_float2(v00, v01);
                *(float2*)&outf[(size_t)(r + 8) * GN + c] = make_float2(v10, v11);
            } else {
                int b = r >> 11, l = r & 2047;
                int h = c >> 7, d = c & 127;
                size_t base = ((size_t)(b * H_HEADS + h) * SEQ + l) * DHEAD + d;
                __half2 h0 = __floats2half2_rn(v00, v01);
                __half2 h1 = __floats2half2_rn(v10, v11);
                *(__half2*)&outp[base]                     = h0;
                *(__half2*)&outp[base + (size_t)8 * DHEAD] = h1;
            }
        }
    }
}

// ---------------------------------------------------------------------------
// Sliding-window flash attention, fp16 mma + ldmatrix.
// 256 threads, 8 warps x 16 query rows. K/V chunks of 64 keys.
// Smem rows: 256B (K/V/Q, 16 chunks) or 128B (P, 8 chunks); chunk c at row r
// stored at c^(r&7) (conflict-free for ldmatrix phases and 16B stores).
// ---------------------------------------------------------------------------
__global__ __launch_bounds__(256, 1)
void attn_h16(const __half* __restrict__ qg, const __half* __restrict__ kg,
              const __half* __restrict__ vg, __half* __restrict__ aout)
{
    __shared__ __align__(16) char sm[49152];
    uint32_t sb = smem_u32(sm);
    uint32_t Ks = sb;                 // 64 x 256B = 16 KB
    uint32_t Vs = sb + 16384;         // 64 x 256B = 16 KB
    uint32_t Ss = sb + 32768;         // 128 x 128B = 16 KB

    int tid = threadIdx.x;
    int wid = tid >> 5, lane = tid & 31, g = lane >> 2, tg = lane & 3;
    int q0 = blockIdx.x * 128;
    int bh = blockIdx.y;
    const __half* qb = qg + (size_t)bh * SEQ * DHEAD;
    const __half* kb = kg + (size_t)bh * SEQ * DHEAD;
    const __half* vb = vg + (size_t)bh * SEQ * DHEAD;
    int b = bh >> 4, h = bh & 15;

    // ---- stage Q (128 x 256B, transient at base of smem) and ldmatrix ----
    #pragma unroll
    for (int e = tid; e < 2048; e += 256) {
        int r = e >> 4, c = e & 15;
        uint4 v = *(const uint4*)&qb[(size_t)(q0 + r) * DHEAD + c * 8];
        *(uint4*)(sm + r * 256 + ((c ^ (r & 7)) * 16)) = v;
    }
    __syncthreads();

    uint32_t qa[8][4];
    {
        int qrow = wid * 16 + (lane & 7) + 8 * ((lane >> 3) & 1);
        #pragma unroll
        for (int ks = 0; ks < 8; ks++) {
            int c = ks * 2 + (lane >> 4);
            ldsm4(qa[ks], sb + qrow * 256 + ((c ^ (qrow & 7)) * 16));
        }
    }
    __syncthreads();

    float o[16][4];
    #pragma unroll
    for (int nt = 0; nt < 16; nt++)
        #pragma unroll
        for (int i = 0; i < 4; i++) o[nt][i] = 0.f;
    float mrow0 = -1e30f, mrow1 = -1e30f, lsum0 = 0.f, lsum1 = 0.f;

    const float scale = 0.088388347648318447f;
    const int offs[6] = {0, 1, -1, -2, -3, -4};   // diagonal chunk FIRST

    // precomputed fragment address components
    int kRow = (lane & 7) + 8 * (lane >> 4);          // B rows for S (K)
    int kK8  = (lane >> 3) & 1;
    int pRow = wid * 16 + (lane & 7) + 8 * ((lane >> 3) & 1);  // A rows for PV (P)
    int pK8  = lane >> 4;
    int vRow = (lane & 7) + 8 * ((lane >> 3) & 1);    // B rows for PV (V, trans)
    int vK8  = lane >> 4;
    int pr0 = wid * 16 + g, pr1 = pr0 + 8;

    for (int ci = 0; ci < 6; ci++) {
        int k0 = q0 + offs[ci] * 64;
        if (k0 < 0) continue;
        __syncthreads();
        // load K,V chunk: 64 rows x 16 chunks each
        #pragma unroll
        for (int e = tid; e < 2048; e += 256) {
            int which = e >> 10, i = e & 1023;
            int r = i >> 4, c = i & 15;
            const __half* src = which ? vb : kb;
            uint4 v = *(const uint4*)&src[(size_t)(k0 + r) * DHEAD + c * 8];
            uint32_t dst = (which ? (16384u) : 0u) + (uint32_t)(r * 256 + ((c ^ (r & 7)) * 16));
            *(uint4*)(sm + dst) = v;
        }
        __syncthreads();

        // ---- S = Q K^T ----
        float s[8][4];
        #pragma unroll
        for (int nt = 0; nt < 8; nt++)
            #pragma unroll
            for (int i = 0; i < 4; i++) s[nt][i] = 0.f;
        #pragma unroll
        for (int ks = 0; ks < 8; ks++) {
            int c = ks * 2 + kK8;
            #pragma unroll
            for (int nq = 0; nq < 4; nq++) {
                int row = nq * 16 + kRow;
                uint32_t bf[4];
                ldsm4(bf, Ks + row * 256 + ((c ^ (row & 7)) * 16));
                mma16(s[2 * nq],     qa[ks], bf[0], bf[1]);
                mma16(s[2 * nq + 1], qa[ks], bf[2], bf[3]);
            }
        }

        // ---- mask + online softmax ----
        int i0 = q0 + pr0, i1 = i0 + 8;
        float mx0 = -1e30f, mx1 = -1e30f;
        #pragma unroll
        for (int nt = 0; nt < 8; nt++) {
            int j0 = k0 + nt * 8 + 2 * tg, j1 = j0 + 1;
            s[nt][0] = ((j0 <= i0) && (j0 > i0 - WIN)) ? s[nt][0] * scale : -1e30f;
            s[nt][1] = ((j1 <= i0) && (j1 > i0 - WIN)) ? s[nt][1] * scale : -1e30f;
            s[nt][2] = ((j0 <= i1) && (j0 > i1 - WIN)) ? s[nt][2] * scale : -1e30f;
            s[nt][3] = ((j1 <= i1) && (j1 > i1 - WIN)) ? s[nt][3] * scale : -1e30f;
            mx0 = fmaxf(mx0, fmaxf(s[nt][0], s[nt][1]));
            mx1 = fmaxf(mx1, fmaxf(s[nt][2], s[nt][3]));
        }
        mx0 = fmaxf(mx0, __shfl_xor_sync(0xffffffffu, mx0, 1));
        mx0 = fmaxf(mx0, __shfl_xor_sync(0xffffffffu, mx0, 2));
        mx1 = fmaxf(mx1, __shfl_xor_sync(0xffffffffu, mx1, 1));
        mx1 = fmaxf(mx1, __shfl_xor_sync(0xffffffffu, mx1, 2));
        float mn0 = fmaxf(mrow0, mx0), mn1 = fmaxf(mrow1, mx1);
        float al0 = __expf(mrow0 - mn0), al1 = __expf(mrow1 - mn1);
        mrow0 = mn0; mrow1 = mn1;

        float rs0 = 0.f, rs1 = 0.f;
        #pragma unroll
        for (int nt = 0; nt < 8; nt++) {
            s[nt][0] = __expf(s[nt][0] - mn0);
            s[nt][1] = __expf(s[nt][1] - mn0);
            s[nt][2] = __expf(s[nt][2] - mn1);
            s[nt][3] = __expf(s[nt][3] - mn1);
            rs0 += s[nt][0] + s[nt][1];
            rs1 += s[nt][2] + s[nt][3];
        }
        rs0 += __shfl_xor_sync(0xffffffffu, rs0, 1);
        rs0 += __shfl_xor_sync(0xffffffffu, rs0, 2);
        rs1 += __shfl_xor_sync(0xffffffffu, rs1, 1);
        rs1 += __shfl_xor_sync(0xffffffffu, rs1, 2);
        lsum0 = lsum0 * al0 + rs0;
        lsum1 = lsum1 * al1 + rs1;

        // ---- P -> fp16 smem (warp-private rows) ----
        #pragma unroll
        for (int nt = 0; nt < 8; nt++) {
            __half2 p0 = __floats2half2_rn(s[nt][0], s[nt][1]);
            __half2 p1 = __floats2half2_rn(s[nt][2], s[nt][3]);
            *(__half2*)(sm + 32768 + pr0 * 128 + ((nt ^ (pr0 & 7)) * 16) + 4 * tg) = p0;
            *(__half2*)(sm + 32768 + pr1 * 128 + ((nt ^ (pr1 & 7)) * 16) + 4 * tg) = p1;
        }
        __syncwarp();

        #pragma unroll
        for (int nt = 0; nt < 16; nt++) {
            o[nt][0] *= al0; o[nt][1] *= al0;
            o[nt][2] *= al1; o[nt][3] *= al1;
        }

        // ---- O += P V ----
        #pragma unroll
        for (int ks = 0; ks < 4; ks++) {
            uint32_t pa[4];
            {
                int c = ks * 2 + pK8;
                ldsm4(pa, Ss + pRow * 128 + ((c ^ (pRow & 7)) * 16));
            }
            int row = ks * 16 + vRow;
            uint32_t vbase = Vs + row * 256;
            int rx = row & 7;
            #pragma unroll
            for (int dt = 0; dt < 8; dt++) {
                int c = dt * 2 + vK8;
                uint32_t bf[4];
                ldsm4t(bf, vbase + ((c ^ rx) * 16));
                mma16(o[2 * dt],     pa, bf[0], bf[1]);
                mma16(o[2 * dt + 1], pa, bf[2], bf[3]);
            }
        }
    }

    float inv0 = 1.f / lsum0, inv1 = 1.f / lsum1;
    int t0 = q0 + pr0;
    #pragma unroll
    for (int nt = 0; nt < 16; nt++) {
        int col = h * DHEAD + nt * 8 + 2 * tg;
        __half2 h0 = __floats2half2_rn(o[nt][0] * inv0, o[nt][1] * inv0);
        __half2 h1 = __floats2half2_rn(o[nt][2] * inv1, o[nt][3] * inv1);
        *(__half2*)&aout[((size_t)b * SEQ + t0) * CDIM + col]     = h0;
        *(__half2*)&aout[((size_t)b * SEQ + t0 + 8) * CDIM + col] = h1;
    }
}

// ---------------------------------------------------------------------------
extern "C" void kernel_launch(void* const* d_in, const int* in_sizes, int n_in,
                              void* d_out, int out_size)
{
    const float* x  = (const float*)d_in[0];
    const float* Wq = (const float*)d_in[1];
    const float* bq = (const float*)d_in[2];
    const float* Wk = (const float*)d_in[3];
    const float* bk = (const float*)d_in[4];
    const float* Wv = (const float*)d_in[5];
    const float* bv = (const float*)d_in[6];
    const float* Wo = (const float*)d_in[7];
    const float* bo = (const float*)d_in[8];
    float* out = (float*)d_out;

    __half *qkvh, *xh, *wh, *aoh;
    cudaGetSymbolAddress((void**)&qkvh, g_qkvh);
    cudaGetSymbolAddress((void**)&xh, g_xh);
    cudaGetSymbolAddress((void**)&wh, g_wh);
    cudaGetSymbolAddress((void**)&aoh, g_aoh);

    cudaFuncSetAttribute(gemm_ca, cudaFuncAttributeMaxDynamicSharedMemorySize, GEMM_SMEM);

    const int XEL = GM * GK;
    const int WEL = (int)WMAT_ELEMS;
    cvt_h<<<XEL / 8 / 256, 256>>>(x, xh, XEL);
    cvt_w4<<<dim3(WEL / 8 / 256, 4), 256>>>(Wq, Wk, Wv, Wo, wh);

    // fused QKV GEMM -> fp16 (B,H,L,D)
    gemm_ca<<<dim3(GM / TBM, 48), 256, GEMM_SMEM>>>(xh, wh, bq, bk, bv, nullptr, qkvh, 1);

    // attention (fp16 in, fp16 out)
    attn_h16<<<dim3(SEQ / 128, BATCH * H_HEADS), 256>>>(
        qkvh, qkvh + QKV_ELEMS, qkvh + 2 * QKV_ELEMS, aoh);

    // output projection -> fp32
    gemm_ca<<<dim3(GM / TBM, GN / TBN), 256, GEMM_SMEM>>>(
        aoh, wh + 3 * WMAT_ELEMS, bo, nullptr, nullptr, out, nullptr, 0);
}